// round 16
// baseline (speedup 1.0000x reference)
#include <cuda_runtime.h>
#include <cuda_bf16.h>

// PointInstanceNorm — R7/R14 three-kernel structure + PDL, round-15 tuning.
// x: [N,D] fp32; seqlen: [B+1] cumulative; weight/bias: [D].
// out[i,d] = (x[i,d]-mean[b,d]) * rsqrt(var[b,d]+eps) * w[d] + bias[d].
//
// R15 changes vs R14 (250.0us):
//  (1) reduce: 3-way unroll (3 independent accumulator chains), single wave
//  (2) norm: prefetch.global.L2 of first 4 iterations BEFORE the PDL
//      dependency sync -> norm's first DRAM fetches overlap finalize
//  (3) reduce: explicit cudaTriggerProgrammaticLaunchCompletion after the
//      partials are published
// Streaming loop bodies otherwise byte-identical to the proven forms.

#define PIN_EPS 1e-5f
#define PIN_MAXBD   (1 << 20)
#define PIN_PARTCAP (1 << 22)

__device__ float g_psum [PIN_PARTCAP];
__device__ float g_psq  [PIN_PARTCAP];
__device__ float g_scale[PIN_MAXBD];
__device__ float g_shift[PIN_MAXBD];
// scalar-fallback scratch
__device__ float g_sum[PIN_MAXBD];
__device__ float g_sq [PIN_MAXBD];

// ---------------------------------------------------------------------------
// Pass 1: reduce. grid=(chunks,B) one wave, block=256, 3-way unroll,
// per-(chunk,b) partials, no atomics.
// ---------------------------------------------------------------------------
__global__ void __launch_bounds__(256)
pin_reduce_kernel(const float* __restrict__ x,
                  const int*   __restrict__ seqlen,
                  int D4, int BD) {
    const int c  = blockIdx.x;
    const int b  = blockIdx.y;
    const long long s = seqlen[b];
    const long long e = seqlen[b + 1];
    const int L  = (int)(e - s);
    const int nb = gridDim.x;
    const int chunk = (L + nb - 1) / nb;
    const long long r0 = s + (long long)c * chunk;
    const long long r1 = s + (long long)min((long long)L,
                                            (long long)(c + 1) * (long long)chunk);
    const int lane = threadIdx.x % D4;
    const int grp  = threadIdx.x / D4;
    const int ngrp = blockDim.x / D4;
    const int D    = D4 * 4;

    float4 s0 = make_float4(0.f, 0.f, 0.f, 0.f), s1 = s0, s2 = s0;
    float4 q0 = s0, q1 = s0, q2 = s0;

    if (grp < ngrp) {
        const float4* __restrict__ x4 = (const float4*)x;
        const long long step = ngrp;
        long long r = r0 + grp;
        for (; r + 2 * step < r1; r += 3 * step) {
            float4 v0 = x4[(r           ) * D4 + lane];
            float4 v1 = x4[(r +     step) * D4 + lane];
            float4 v2 = x4[(r + 2 * step) * D4 + lane];
            s0.x += v0.x; s0.y += v0.y; s0.z += v0.z; s0.w += v0.w;
            q0.x += v0.x * v0.x; q0.y += v0.y * v0.y;
            q0.z += v0.z * v0.z; q0.w += v0.w * v0.w;
            s1.x += v1.x; s1.y += v1.y; s1.z += v1.z; s1.w += v1.w;
            q1.x += v1.x * v1.x; q1.y += v1.y * v1.y;
            q1.z += v1.z * v1.z; q1.w += v1.w * v1.w;
            s2.x += v2.x; s2.y += v2.y; s2.z += v2.z; s2.w += v2.w;
            q2.x += v2.x * v2.x; q2.y += v2.y * v2.y;
            q2.z += v2.z * v2.z; q2.w += v2.w * v2.w;
        }
        for (; r < r1; r += step) {
            float4 v = x4[r * D4 + lane];
            s0.x += v.x; s0.y += v.y; s0.z += v.z; s0.w += v.w;
            q0.x += v.x * v.x; q0.y += v.y * v.y;
            q0.z += v.z * v.z; q0.w += v.w * v.w;
        }
    }
    s0.x += s1.x + s2.x; s0.y += s1.y + s2.y;
    s0.z += s1.z + s2.z; s0.w += s1.w + s2.w;
    q0.x += q1.x + q2.x; q0.y += q1.y + q2.y;
    q0.z += q1.z + q2.z; q0.w += q1.w + q2.w;

    __shared__ float4 sh_s[256];
    __shared__ float4 sh_q[256];
    sh_s[threadIdx.x] = s0;
    sh_q[threadIdx.x] = q0;
    __syncthreads();

    if (grp == 0) {
        for (int g = 1; g < ngrp; g++) {
            float4 a  = sh_s[g * D4 + lane];
            float4 cq = sh_q[g * D4 + lane];
            s0.x += a.x;  s0.y += a.y;  s0.z += a.z;  s0.w += a.w;
            q0.x += cq.x; q0.y += cq.y; q0.z += cq.z; q0.w += cq.w;
        }
        const long long o = (long long)c * BD + b * D + lane * 4;
        ((float4*)(g_psum + o))[0] = s0;
        ((float4*)(g_psq  + o))[0] = q0;
    }

#if __CUDA_ARCH__ >= 900
    __syncthreads();                       // partials published by this block
    cudaTriggerProgrammaticLaunchCompletion();
#endif
}

// ---------------------------------------------------------------------------
// Finalize: sum partials over chunks -> scale/shift. PDL: waits on reduce.
// ---------------------------------------------------------------------------
__global__ void pin_finalize_kernel(const int*   __restrict__ seqlen,
                                    const float* __restrict__ w,
                                    const float* __restrict__ bias,
                                    int B, int D, int chunks) {
    int i = blockIdx.x * blockDim.x + threadIdx.x;
    int BD = B * D;

#if __CUDA_ARCH__ >= 900
    cudaGridDependencySynchronize();
#endif
    if (i >= BD) return;
    int b = i / D;
    int d = i - b * D;

    float sum = 0.f, sq = 0.f;
    for (int c = 0; c < chunks; c++) {
        long long o = (long long)c * BD + i;
        sum += g_psum[o];
        sq  += g_psq [o];
    }
    float denom = fmaxf((float)(seqlen[b + 1] - seqlen[b]), 1.0f);
    float mean  = sum / denom;
    float var   = fmaxf(sq / denom - mean * mean, 0.0f);
    float sc = rsqrtf(var + PIN_EPS) * w[d];
    g_scale[i] = sc;
    g_shift[i] = bias[d] - mean * sc;
}

// ---------------------------------------------------------------------------
// Pass 2: normalize — R3/R7 streaming loop. PDL: prefetch first rows into
// L2 BEFORE the dependency sync (x is an input, independent of finalize).
// ---------------------------------------------------------------------------
__global__ void __launch_bounds__(256)
pin_norm_kernel(const float* __restrict__ x,
                const int*   __restrict__ seqlen,
                float*       __restrict__ out,
                int D4) {
    const int b = blockIdx.y;
    const long long s = seqlen[b];
    const long long e = seqlen[b + 1];
    const int L  = (int)(e - s);
    const int nb = gridDim.x;
    const int chunk = (L + nb - 1) / nb;
    const long long r0 = s + (long long)blockIdx.x * chunk;
    const long long r1 = s + (long long)min((long long)L,
                                            (long long)(blockIdx.x + 1) * (long long)chunk);
    const int lane = threadIdx.x % D4;
    const int grp  = threadIdx.x / D4;
    const int ngrp = blockDim.x / D4;
    if (grp >= ngrp) return;

    const float4* __restrict__ x4 = (const float4*)x;
    float4* __restrict__ o4 = (float4*)out;

#if __CUDA_ARCH__ >= 900
    // Warm L2 with this thread's first rows while finalize runs.
    #pragma unroll
    for (int p = 0; p < 4; p++) {
        long long rr = r0 + grp + (long long)p * ngrp;
        if (rr < r1) {
            const float4* addr = x4 + rr * D4 + lane;
            asm volatile("prefetch.global.L2 [%0];" :: "l"(addr));
        }
    }
    cudaGridDependencySynchronize();     // g_scale/g_shift now valid
#endif

    const float4 sc = ((const float4*)g_scale)[b * D4 + lane];
    const float4 sh = ((const float4*)g_shift)[b * D4 + lane];

    for (long long r = r0 + grp; r < r1; r += ngrp) {
        float4 v = x4[r * D4 + lane];
        float4 o;
        o.x = fmaf(v.x, sc.x, sh.x);
        o.y = fmaf(v.y, sc.y, sh.y);
        o.z = fmaf(v.z, sc.z, sh.z);
        o.w = fmaf(v.w, sc.w, sh.w);
        o4[r * D4 + lane] = o;
    }
}

// ---------------------------------------------------------------------------
// Scalar fallback (any shape).
// ---------------------------------------------------------------------------
__global__ void pin_zero_kernel(int n) {
    int i = blockIdx.x * blockDim.x + threadIdx.x;
    if (i < n) { g_sum[i] = 0.0f; g_sq[i] = 0.0f; }
}

__global__ void pin_reduce_scalar(const float* __restrict__ x,
                                  const int*   __restrict__ seqlen, int D) {
    const int b = blockIdx.y;
    const int s = seqlen[b];
    const int e = seqlen[b + 1];
    const int L = e - s;
    const int nb = gridDim.x;
    const int chunk = (L + nb - 1) / nb;
    long long r0 = (long long)s + (long long)blockIdx.x * chunk;
    long long r1 = (long long)s + (long long)min((long long)L,
                                                 (long long)(blockIdx.x + 1) * (long long)chunk);
    for (int d = threadIdx.x; d < D; d += blockDim.x) {
        float sum = 0.f, sq = 0.f;
        for (long long r = r0; r < r1; r++) {
            float v = x[r * D + d];
            sum += v; sq += v * v;
        }
        atomicAdd(&g_sum[b * D + d], sum);
        atomicAdd(&g_sq [b * D + d], sq);
    }
}

__global__ void pin_finalize_scalar(const int*   __restrict__ seqlen,
                                    const float* __restrict__ w,
                                    const float* __restrict__ bias,
                                    int B, int D) {
    int i = blockIdx.x * blockDim.x + threadIdx.x;
    if (i >= B * D) return;
    int b = i / D;
    int d = i - b * D;
    float denom = fmaxf((float)(seqlen[b + 1] - seqlen[b]), 1.0f);
    float mean  = g_sum[i] / denom;
    float var   = fmaxf(g_sq[i] / denom - mean * mean, 0.0f);
    float sc = rsqrtf(var + PIN_EPS) * w[d];
    g_scale[i] = sc;
    g_shift[i] = bias[d] - mean * sc;
}

__global__ void pin_norm_scalar(const float* __restrict__ x,
                                const int*   __restrict__ seqlen,
                                float*       __restrict__ out, int D) {
    const int b = blockIdx.y;
    const int s = seqlen[b];
    const int e = seqlen[b + 1];
    const int L = e - s;
    const int nb = gridDim.x;
    const int chunk = (L + nb - 1) / nb;
    long long r0 = (long long)s + (long long)blockIdx.x * chunk;
    long long r1 = (long long)s + (long long)min((long long)L,
                                                 (long long)(blockIdx.x + 1) * (long long)chunk);
    for (long long r = r0; r < r1; r++) {
        for (int d = threadIdx.x; d < D; d += blockDim.x) {
            float v = x[r * D + d];
            out[r * D + d] = fmaf(v, g_scale[b * D + d], g_shift[b * D + d]);
        }
    }
}

// Launch helper: kernel with programmatic stream serialization (PDL).
template <typename... Args>
static void launch_pdl(void (*kern)(Args...), dim3 grid, dim3 block,
                       Args... args) {
    cudaLaunchConfig_t cfg = {};
    cfg.gridDim = grid;
    cfg.blockDim = block;
    cfg.dynamicSmemBytes = 0;
    cfg.stream = 0;
    cudaLaunchAttribute attr[1];
    attr[0].id = cudaLaunchAttributeProgrammaticStreamSerialization;
    attr[0].val.programmaticStreamSerializationAllowed = 1;
    cfg.attrs = attr;
    cfg.numAttrs = 1;
    cudaError_t err = cudaLaunchKernelEx(&cfg, kern, args...);
    if (err != cudaSuccess) {
        // Fallback: plain serial launch (same semantics, no overlap)
        cudaGetLastError();
        void* params[] = { (void*)&args... };
        cudaLaunchKernel((const void*)kern, grid, block, params, 0, 0);
    }
}

extern "C" void kernel_launch(void* const* d_in, const int* in_sizes, int n_in,
                              void* d_out, int out_size) {
    const float* x      = (const float*)d_in[0];
    const int*   seqlen = (const int*)  d_in[1];
    const float* weight = (const float*)d_in[2];
    const float* bias   = (const float*)d_in[3];
    float*       out    = (float*)d_out;

    const int D  = in_sizes[2];          // weight is [1, D]
    const int B  = in_sizes[1] - 1;      // seqlen is [B+1]
    const long long N = (D > 0) ? (long long)in_sizes[0] / D : 0;
    const int BD = B * D;

    const int D4 = D / 4;
    const bool vec_ok = (D > 0) && (D % 4 == 0) && (D4 >= 1) && (D4 <= 256) &&
                        (BD > 0) && (BD <= PIN_MAXBD);

    if (vec_ok) {
        // ---- reduce: one resident wave ----
        int dev = 0, sms = 0, per_sm = 0;
        cudaGetDevice(&dev);
        cudaDeviceGetAttribute(&sms, cudaDevAttrMultiProcessorCount, dev);
        cudaOccupancyMaxActiveBlocksPerMultiprocessor(&per_sm, pin_reduce_kernel,
                                                      256, 0);
        if (sms <= 0) sms = 148;
        if (per_sm <= 0) per_sm = 4;
        int rchunks = (sms * per_sm) / B;            // one wave total
        if (rchunks < 1) rchunks = 1;
        long long avg_rows = (N + B - 1) / B;
        if ((long long)rchunks > avg_rows && avg_rows > 0)
            rchunks = (int)avg_rows;
        while ((long long)rchunks * BD > PIN_PARTCAP && rchunks > 1)
            rchunks >>= 1;

        // ---- norm: R3 config (~4096 blocks) ----
        int nchunks = (4096 + B - 1) / B;
        if ((long long)nchunks > avg_rows && avg_rows > 0)
            nchunks = (int)avg_rows;
        if (nchunks < 1) nchunks = 1;

        dim3 rgrid(rchunks, B);
        dim3 ngrid(nchunks, B);

        pin_reduce_kernel<<<rgrid, 256>>>(x, seqlen, D4, BD);

        {
            int threads = 256;
            int blocks = (BD + threads - 1) / threads;
            launch_pdl(pin_finalize_kernel, dim3(blocks), dim3(threads),
                       seqlen, weight, bias, B, D, rchunks);
        }
        launch_pdl(pin_norm_kernel, ngrid, dim3(256),
                   x, seqlen, out, D4);
        return;
    }

    // ---- Fallback: scalar 4-kernel pipeline (any shape) ----
    {
        int threads = 256;
        int blocks = (BD + threads - 1) / threads;
        if (blocks < 1) blocks = 1;
        pin_zero_kernel<<<blocks, threads>>>(BD);
    }
    int Bx = (B > 0) ? B : 1;
    int ch = (4096 + Bx - 1) / Bx;
    long long avg_rows = (N + Bx - 1) / Bx;
    if ((long long)ch > avg_rows && avg_rows > 0) ch = (int)avg_rows;
    if (ch < 1) ch = 1;
    dim3 grid(ch, Bx);
    pin_reduce_scalar<<<grid, 256>>>(x, seqlen, D);
    {
        int threads = 256;
        int blocks = (BD + threads - 1) / threads;
        if (blocks < 1) blocks = 1;
        pin_finalize_scalar<<<blocks, threads>>>(seqlen, weight, bias, B, D);
    }
    pin_norm_scalar<<<grid, 256>>>(x, seqlen, out, D);
}

// round 17
// speedup vs baseline: 1.0143x; 1.0143x over previous
#include <cuda_runtime.h>
#include <cuda_bf16.h>

// PointInstanceNorm — three kernels + PDL. Round-16: keep R15's 3-way-unroll
// reduce (79.8us @6.46TB/s) and PDL launches; REMOVE the norm prefetch
// prologue that cost ~4.7us (norm body back to the exact R3/R14 form).
// x: [N,D] fp32; seqlen: [B+1] cumulative; weight/bias: [D].
// out[i,d] = (x[i,d]-mean[b,d]) * rsqrt(var[b,d]+eps) * w[d] + bias[d].

#define PIN_EPS 1e-5f
#define PIN_MAXBD   (1 << 20)
#define PIN_PARTCAP (1 << 22)

__device__ float g_psum [PIN_PARTCAP];
__device__ float g_psq  [PIN_PARTCAP];
__device__ float g_scale[PIN_MAXBD];
__device__ float g_shift[PIN_MAXBD];
// scalar-fallback scratch
__device__ float g_sum[PIN_MAXBD];
__device__ float g_sq [PIN_MAXBD];

// ---------------------------------------------------------------------------
// Pass 1: reduce — R15 form (3-way unroll, single wave, no atomics).
// ---------------------------------------------------------------------------
__global__ void __launch_bounds__(256)
pin_reduce_kernel(const float* __restrict__ x,
                  const int*   __restrict__ seqlen,
                  int D4, int BD) {
    const int c  = blockIdx.x;
    const int b  = blockIdx.y;
    const long long s = seqlen[b];
    const long long e = seqlen[b + 1];
    const int L  = (int)(e - s);
    const int nb = gridDim.x;
    const int chunk = (L + nb - 1) / nb;
    const long long r0 = s + (long long)c * chunk;
    const long long r1 = s + (long long)min((long long)L,
                                            (long long)(c + 1) * (long long)chunk);
    const int lane = threadIdx.x % D4;
    const int grp  = threadIdx.x / D4;
    const int ngrp = blockDim.x / D4;
    const int D    = D4 * 4;

    float4 s0 = make_float4(0.f, 0.f, 0.f, 0.f), s1 = s0, s2 = s0;
    float4 q0 = s0, q1 = s0, q2 = s0;

    if (grp < ngrp) {
        const float4* __restrict__ x4 = (const float4*)x;
        const long long step = ngrp;
        long long r = r0 + grp;
        for (; r + 2 * step < r1; r += 3 * step) {
            float4 v0 = x4[(r           ) * D4 + lane];
            float4 v1 = x4[(r +     step) * D4 + lane];
            float4 v2 = x4[(r + 2 * step) * D4 + lane];
            s0.x += v0.x; s0.y += v0.y; s0.z += v0.z; s0.w += v0.w;
            q0.x += v0.x * v0.x; q0.y += v0.y * v0.y;
            q0.z += v0.z * v0.z; q0.w += v0.w * v0.w;
            s1.x += v1.x; s1.y += v1.y; s1.z += v1.z; s1.w += v1.w;
            q1.x += v1.x * v1.x; q1.y += v1.y * v1.y;
            q1.z += v1.z * v1.z; q1.w += v1.w * v1.w;
            s2.x += v2.x; s2.y += v2.y; s2.z += v2.z; s2.w += v2.w;
            q2.x += v2.x * v2.x; q2.y += v2.y * v2.y;
            q2.z += v2.z * v2.z; q2.w += v2.w * v2.w;
        }
        for (; r < r1; r += step) {
            float4 v = x4[r * D4 + lane];
            s0.x += v.x; s0.y += v.y; s0.z += v.z; s0.w += v.w;
            q0.x += v.x * v.x; q0.y += v.y * v.y;
            q0.z += v.z * v.z; q0.w += v.w * v.w;
        }
    }
    s0.x += s1.x + s2.x; s0.y += s1.y + s2.y;
    s0.z += s1.z + s2.z; s0.w += s1.w + s2.w;
    q0.x += q1.x + q2.x; q0.y += q1.y + q2.y;
    q0.z += q1.z + q2.z; q0.w += q1.w + q2.w;

    __shared__ float4 sh_s[256];
    __shared__ float4 sh_q[256];
    sh_s[threadIdx.x] = s0;
    sh_q[threadIdx.x] = q0;
    __syncthreads();

    if (grp == 0) {
        for (int g = 1; g < ngrp; g++) {
            float4 a  = sh_s[g * D4 + lane];
            float4 cq = sh_q[g * D4 + lane];
            s0.x += a.x;  s0.y += a.y;  s0.z += a.z;  s0.w += a.w;
            q0.x += cq.x; q0.y += cq.y; q0.z += cq.z; q0.w += cq.w;
        }
        const long long o = (long long)c * BD + b * D + lane * 4;
        ((float4*)(g_psum + o))[0] = s0;
        ((float4*)(g_psq  + o))[0] = q0;
    }

#if __CUDA_ARCH__ >= 900
    __syncthreads();                       // partials published by this block
    cudaTriggerProgrammaticLaunchCompletion();
#endif
}

// ---------------------------------------------------------------------------
// Finalize: sum partials over chunks -> scale/shift. PDL: waits on reduce.
// ---------------------------------------------------------------------------
__global__ void pin_finalize_kernel(const int*   __restrict__ seqlen,
                                    const float* __restrict__ w,
                                    const float* __restrict__ bias,
                                    int B, int D, int chunks) {
    int i = blockIdx.x * blockDim.x + threadIdx.x;
    int BD = B * D;

#if __CUDA_ARCH__ >= 900
    cudaGridDependencySynchronize();
#endif
    if (i >= BD) return;
    int b = i / D;
    int d = i - b * D;

    float sum = 0.f, sq = 0.f;
    for (int c = 0; c < chunks; c++) {
        long long o = (long long)c * BD + i;
        sum += g_psum[o];
        sq  += g_psq [o];
    }
    float denom = fmaxf((float)(seqlen[b + 1] - seqlen[b]), 1.0f);
    float mean  = sum / denom;
    float var   = fmaxf(sq / denom - mean * mean, 0.0f);
    float sc = rsqrtf(var + PIN_EPS) * w[d];
    g_scale[i] = sc;
    g_shift[i] = bias[d] - mean * sc;
}

// ---------------------------------------------------------------------------
// Pass 2: normalize — EXACT R3/R14 streaming form (151.7us proven).
// Only addition: PDL dependency sync at top. NO prefetch prologue.
// ---------------------------------------------------------------------------
__global__ void __launch_bounds__(256)
pin_norm_kernel(const float* __restrict__ x,
                const int*   __restrict__ seqlen,
                float*       __restrict__ out,
                int D4) {
    const int b = blockIdx.y;
    const long long s = seqlen[b];
    const long long e = seqlen[b + 1];
    const int L  = (int)(e - s);
    const int nb = gridDim.x;
    const int chunk = (L + nb - 1) / nb;
    const long long r0 = s + (long long)blockIdx.x * chunk;
    const long long r1 = s + (long long)min((long long)L,
                                            (long long)(blockIdx.x + 1) * (long long)chunk);
    const int lane = threadIdx.x % D4;
    const int grp  = threadIdx.x / D4;
    const int ngrp = blockDim.x / D4;
    if (grp >= ngrp) return;

#if __CUDA_ARCH__ >= 900
    cudaGridDependencySynchronize();     // g_scale/g_shift now valid
#endif
    const float4 sc = ((const float4*)g_scale)[b * D4 + lane];
    const float4 sh = ((const float4*)g_shift)[b * D4 + lane];
    const float4* __restrict__ x4 = (const float4*)x;
    float4* __restrict__ o4 = (float4*)out;

    for (long long r = r0 + grp; r < r1; r += ngrp) {
        float4 v = x4[r * D4 + lane];
        float4 o;
        o.x = fmaf(v.x, sc.x, sh.x);
        o.y = fmaf(v.y, sc.y, sh.y);
        o.z = fmaf(v.z, sc.z, sh.z);
        o.w = fmaf(v.w, sc.w, sh.w);
        o4[r * D4 + lane] = o;
    }
}

// ---------------------------------------------------------------------------
// Scalar fallback (any shape).
// ---------------------------------------------------------------------------
__global__ void pin_zero_kernel(int n) {
    int i = blockIdx.x * blockDim.x + threadIdx.x;
    if (i < n) { g_sum[i] = 0.0f; g_sq[i] = 0.0f; }
}

__global__ void pin_reduce_scalar(const float* __restrict__ x,
                                  const int*   __restrict__ seqlen, int D) {
    const int b = blockIdx.y;
    const int s = seqlen[b];
    const int e = seqlen[b + 1];
    const int L = e - s;
    const int nb = gridDim.x;
    const int chunk = (L + nb - 1) / nb;
    long long r0 = (long long)s + (long long)blockIdx.x * chunk;
    long long r1 = (long long)s + (long long)min((long long)L,
                                                 (long long)(blockIdx.x + 1) * (long long)chunk);
    for (int d = threadIdx.x; d < D; d += blockDim.x) {
        float sum = 0.f, sq = 0.f;
        for (long long r = r0; r < r1; r++) {
            float v = x[r * D + d];
            sum += v; sq += v * v;
        }
        atomicAdd(&g_sum[b * D + d], sum);
        atomicAdd(&g_sq [b * D + d], sq);
    }
}

__global__ void pin_finalize_scalar(const int*   __restrict__ seqlen,
                                    const float* __restrict__ w,
                                    const float* __restrict__ bias,
                                    int B, int D) {
    int i = blockIdx.x * blockDim.x + threadIdx.x;
    if (i >= B * D) return;
    int b = i / D;
    int d = i - b * D;
    float denom = fmaxf((float)(seqlen[b + 1] - seqlen[b]), 1.0f);
    float mean  = g_sum[i] / denom;
    float var   = fmaxf(g_sq[i] / denom - mean * mean, 0.0f);
    float sc = rsqrtf(var + PIN_EPS) * w[d];
    g_scale[i] = sc;
    g_shift[i] = bias[d] - mean * sc;
}

__global__ void pin_norm_scalar(const float* __restrict__ x,
                                const int*   __restrict__ seqlen,
                                float*       __restrict__ out, int D) {
    const int b = blockIdx.y;
    const int s = seqlen[b];
    const int e = seqlen[b + 1];
    const int L = e - s;
    const int nb = gridDim.x;
    const int chunk = (L + nb - 1) / nb;
    long long r0 = (long long)s + (long long)blockIdx.x * chunk;
    long long r1 = (long long)s + (long long)min((long long)L,
                                                 (long long)(blockIdx.x + 1) * (long long)chunk);
    for (long long r = r0; r < r1; r++) {
        for (int d = threadIdx.x; d < D; d += blockDim.x) {
            float v = x[r * D + d];
            out[r * D + d] = fmaf(v, g_scale[b * D + d], g_shift[b * D + d]);
        }
    }
}

// Launch helper: kernel with programmatic stream serialization (PDL).
template <typename... Args>
static void launch_pdl(void (*kern)(Args...), dim3 grid, dim3 block,
                       Args... args) {
    cudaLaunchConfig_t cfg = {};
    cfg.gridDim = grid;
    cfg.blockDim = block;
    cfg.dynamicSmemBytes = 0;
    cfg.stream = 0;
    cudaLaunchAttribute attr[1];
    attr[0].id = cudaLaunchAttributeProgrammaticStreamSerialization;
    attr[0].val.programmaticStreamSerializationAllowed = 1;
    cfg.attrs = attr;
    cfg.numAttrs = 1;
    cudaError_t err = cudaLaunchKernelEx(&cfg, kern, args...);
    if (err != cudaSuccess) {
        // Fallback: plain serial launch (same semantics, no overlap)
        cudaGetLastError();
        void* params[] = { (void*)&args... };
        cudaLaunchKernel((const void*)kern, grid, block, params, 0, 0);
    }
}

extern "C" void kernel_launch(void* const* d_in, const int* in_sizes, int n_in,
                              void* d_out, int out_size) {
    const float* x      = (const float*)d_in[0];
    const int*   seqlen = (const int*)  d_in[1];
    const float* weight = (const float*)d_in[2];
    const float* bias   = (const float*)d_in[3];
    float*       out    = (float*)d_out;

    const int D  = in_sizes[2];          // weight is [1, D]
    const int B  = in_sizes[1] - 1;      // seqlen is [B+1]
    const long long N = (D > 0) ? (long long)in_sizes[0] / D : 0;
    const int BD = B * D;

    const int D4 = D / 4;
    const bool vec_ok = (D > 0) && (D % 4 == 0) && (D4 >= 1) && (D4 <= 256) &&
                        (BD > 0) && (BD <= PIN_MAXBD);

    if (vec_ok) {
        // ---- reduce: one resident wave ----
        int dev = 0, sms = 0, per_sm = 0;
        cudaGetDevice(&dev);
        cudaDeviceGetAttribute(&sms, cudaDevAttrMultiProcessorCount, dev);
        cudaOccupancyMaxActiveBlocksPerMultiprocessor(&per_sm, pin_reduce_kernel,
                                                      256, 0);
        if (sms <= 0) sms = 148;
        if (per_sm <= 0) per_sm = 4;
        int rchunks = (sms * per_sm) / B;            // one wave total
        if (rchunks < 1) rchunks = 1;
        long long avg_rows = (N + B - 1) / B;
        if ((long long)rchunks > avg_rows && avg_rows > 0)
            rchunks = (int)avg_rows;
        while ((long long)rchunks * BD > PIN_PARTCAP && rchunks > 1)
            rchunks >>= 1;

        // ---- norm: R3 config (~4096 blocks) ----
        int nchunks = (4096 + B - 1) / B;
        if ((long long)nchunks > avg_rows && avg_rows > 0)
            nchunks = (int)avg_rows;
        if (nchunks < 1) nchunks = 1;

        dim3 rgrid(rchunks, B);
        dim3 ngrid(nchunks, B);

        pin_reduce_kernel<<<rgrid, 256>>>(x, seqlen, D4, BD);

        {
            int threads = 256;
            int blocks = (BD + threads - 1) / threads;
            launch_pdl(pin_finalize_kernel, dim3(blocks), dim3(threads),
                       seqlen, weight, bias, B, D, rchunks);
        }
        launch_pdl(pin_norm_kernel, ngrid, dim3(256),
                   x, seqlen, out, D4);
        return;
    }

    // ---- Fallback: scalar 4-kernel pipeline (any shape) ----
    {
        int threads = 256;
        int blocks = (BD + threads - 1) / threads;
        if (blocks < 1) blocks = 1;
        pin_zero_kernel<<<blocks, threads>>>(BD);
    }
    int Bx = (B > 0) ? B : 1;
    int ch = (4096 + Bx - 1) / Bx;
    long long avg_rows = (N + Bx - 1) / Bx;
    if ((long long)ch > avg_rows && avg_rows > 0) ch = (int)avg_rows;
    if (ch < 1) ch = 1;
    dim3 grid(ch, Bx);
    pin_reduce_scalar<<<grid, 256>>>(x, seqlen, D);
    {
        int threads = 256;
        int blocks = (BD + threads - 1) / threads;
        if (blocks < 1) blocks = 1;
        pin_finalize_scalar<<<blocks, threads>>>(seqlen, weight, bias, B, D);
    }
    pin_norm_scalar<<<grid, 256>>>(x, seqlen, out, D);
}